// round 16
// baseline (speedup 1.0000x reference)
#include <cuda_runtime.h>
#include <cuda_bf16.h>
#include <stdint.h>

#define N_HALF 4096
#define N_TOT  8192
#define DIM    512
#define TILE   128
#define NCHUNK 8
#define GRID_T 64
#define NUM_TILES 2080
#define CONV_CTAS (N_TOT / 8)
#define CS_CTAS 64
#define STRIPES 16
#define PITCH 516

__device__ __nv_bfloat16 g_hi[(size_t)N_TOT * DIM];
__device__ float g_sq[N_TOT];
__device__ float g_colpart[STRIPES][DIM];   // statically zero-init; self-cleaned
__device__ float g_coef;
__device__ float g_partials[NUM_TILES];
__device__ int g_cs_done;                   // self-cleaned

__device__ __forceinline__ uint32_t smem_u32_of(const void* p) {
    uint32_t a;
    asm("{ .reg .u64 t; cvta.to.shared.u64 t, %1; cvt.u32.u64 %0, t; }" : "=r"(a) : "l"(p));
    return a;
}

#define LDSM_X4(r, addr)                                                       \
    asm volatile("ldmatrix.sync.aligned.m8n8.x4.shared.b16 {%0,%1,%2,%3}, [%4];" \
        : "=r"((r)[0]), "=r"((r)[1]), "=r"((r)[2]), "=r"((r)[3]) : "r"(addr))

#define MMA_BF16(c, a, b0, b1)                                                 \
    asm volatile("mma.sync.aligned.m16n8k16.row.col.f32.bf16.bf16.f32 "        \
        "{%0,%1,%2,%3},{%4,%5,%6,%7},{%8,%9},{%0,%1,%2,%3};"                   \
        : "+f"((c)[0]), "+f"((c)[1]), "+f"((c)[2]), "+f"((c)[3])               \
        : "r"((a)[0]), "r"((a)[1]), "r"((a)[2]), "r"((a)[3]), "r"(b0), "r"(b1))

// ---------------- mmd smem map (bytes) ----------------
#define SM_TILE    16384
#define SM_STAGE   32768
#define SM_SQA     98304
#define SM_SQB     (SM_SQA + 512)
#define SM_RED     (SM_SQB + 512)
#define SMEM_TOTAL (SM_RED + 1024)

// --------- convert: pure stream fp32 -> bf16 + rounded row norms -------------
__global__ __launch_bounds__(256) void convert_kernel(const float* __restrict__ src,
                                                      const float* __restrict__ tgt) {
    __shared__ float stage[8 * PITCH];
    int tid = threadIdx.x, w = tid >> 5, lane = tid & 31;
    int row0 = blockIdx.x * 8;
    const float* base = (row0 < N_HALF) ? src + (size_t)row0 * DIM
                                        : tgt + (size_t)(row0 - N_HALF) * DIM;
    uint32_t sstage = smem_u32_of(stage);
#pragma unroll
    for (int m = 0; m < 4; m++) {
        int u = tid + 256 * m;
        int r = u >> 7, j = u & 127;
        const char* gp = (const char*)(base + (size_t)r * DIM) + j * 16;
        uint32_t dst = sstage + (uint32_t)(r * PITCH * 4 + j * 16);
        asm volatile("cp.async.cg.shared.global [%0], [%1], 16;" :: "r"(dst), "l"(gp));
    }
    asm volatile("cp.async.commit_group;" ::: "memory");
    asm volatile("cp.async.wait_group 0;" ::: "memory");
    __syncthreads();

    const float4* rp = (const float4*)(stage + w * PITCH + lane * 16);
    float4 v0 = rp[0], v1 = rp[1], v2 = rp[2], v3 = rp[3];
    float f[16];
    f[0]=v0.x; f[1]=v0.y; f[2]=v0.z; f[3]=v0.w;
    f[4]=v1.x; f[5]=v1.y; f[6]=v1.z; f[7]=v1.w;
    f[8]=v2.x; f[9]=v2.y; f[10]=v2.z; f[11]=v2.w;
    f[12]=v3.x; f[13]=v3.y; f[14]=v3.z; f[15]=v3.w;
    uint32_t packed[8];
    float sq = 0.f;
#pragma unroll
    for (int k = 0; k < 8; k++) {
        __nv_bfloat16 ha = __float2bfloat16(f[2 * k]);
        __nv_bfloat16 hb = __float2bfloat16(f[2 * k + 1]);
        float fa = __bfloat162float(ha);
        float fb = __bfloat162float(hb);
        sq += fa * fa + fb * fb;
        __nv_bfloat162 h2; h2.x = ha; h2.y = hb;
        packed[k] = *(uint32_t*)&h2;
    }
    uint4* dst = (uint4*)(g_hi + (size_t)(row0 + w) * DIM + lane * 16);
    dst[0] = make_uint4(packed[0], packed[1], packed[2], packed[3]);
    dst[1] = make_uint4(packed[4], packed[5], packed[6], packed[7]);
#pragma unroll
    for (int o = 16; o; o >>= 1) sq += __shfl_xor_sync(0xffffffffu, sq, o);
    if (lane == 0) g_sq[row0 + w] = sq;
}

// --------- colsum (from rounded g_hi) + bandwidth tail ------------------------
__global__ __launch_bounds__(256) void colsum_bw_kernel() {
    __shared__ float cbuf[8][DIM + 8];
    __shared__ int is_last;
    __shared__ double shd[256];
    int tid = threadIdx.x, w = tid >> 5, lane = tid & 31;
    int row0 = blockIdx.x * 128;

    float cs[16];
#pragma unroll
    for (int i = 0; i < 16; i++) cs[i] = 0.f;
    // warp w: rows row0 + w + 8k, k=0..15; lane owns cols [lane*16, +16)
    for (int k = 0; k < 16; k++) {
        int row = row0 + w + 8 * k;
        const uint4* p = (const uint4*)(g_hi + (size_t)row * DIM + lane * 16);
        uint4 a = p[0], b = p[1];
        uint32_t u[8] = {a.x, a.y, a.z, a.w, b.x, b.y, b.z, b.w};
#pragma unroll
        for (int j = 0; j < 8; j++) {
            float2 fv = __bfloat1622float2(*(__nv_bfloat162*)&u[j]);
            cs[2 * j] += fv.x;
            cs[2 * j + 1] += fv.y;
        }
    }
#pragma unroll
    for (int j = 0; j < 16; j++) cbuf[w][lane * 16 + j] = cs[j];
    __syncthreads();

    int stripe = blockIdx.x & (STRIPES - 1);
    for (int c = tid; c < DIM; c += 256) {
        float s = 0.f;
#pragma unroll
        for (int r = 0; r < 8; r++) s += cbuf[r][c];
        atomicAdd(&g_colpart[stripe][c], s);
    }

    // ---- last-CTA-done: compute bandwidth coefficient ----
    if (tid == 0) {
        __threadfence();
        int d = atomicAdd(&g_cs_done, 1);
        is_last = (d == CS_CTAS - 1);
    }
    __syncthreads();
    if (!is_last) return;
    __threadfence();

    double acc = 0.0;
    for (int i = tid; i < N_TOT; i += 256) acc += (double)g_sq[i];
    shd[tid] = acc; __syncthreads();
    for (int o = 128; o; o >>= 1) { if (tid < o) shd[tid] += shd[tid + o]; __syncthreads(); }
    double sumsq = shd[0];
    __syncthreads();
    double acc2 = 0.0;
    for (int i = tid; i < DIM; i += 256) {
        double c = 0.0;
#pragma unroll
        for (int st = 0; st < STRIPES; st++) c += (double)g_colpart[st][i];
        acc2 += c * c;
    }
    shd[tid] = acc2; __syncthreads();
    for (int o = 128; o; o >>= 1) { if (tid < o) shd[tid] += shd[tid + o]; __syncthreads(); }
    if (tid == 0) {
        double ss = shd[0];
        double sumL2 = 2.0 * (double)N_TOT * sumsq - 2.0 * ss;
        double bw = sumL2 / ((double)N_TOT * (double)N_TOT - (double)N_TOT);
        g_coef = (float)(-1.4426950408889634 / (4.0 * bw));
        g_cs_done = 0;                     // self-clean
    }
    for (int i = tid; i < STRIPES * DIM; i += 256)
        ((float*)g_colpart)[i] = 0.f;      // self-clean
}

// ---------------- async tile loader (2 tiles: Ahi, Bhi) ----------------
__device__ __forceinline__ void load_chunk_async(uint32_t sbase, uint32_t stage, int c,
                                                 int rowA0, int rowB0, int tid) {
#pragma unroll
    for (int m = 0; m < 8; m++) {
        int u = tid + 256 * m;
        int t = u >> 10;            // 0: Ahi, 1: Bhi
        int v = u & 1023;
        int r = v >> 3;             // row 0..127
        int i16 = v & 7;            // 16B group within 128B row
        int grow = ((t == 0) ? rowA0 : rowB0) + r;
        const char* gp = (const char*)(g_hi + (size_t)grow * DIM) + c * 128 + i16 * 16;
        uint32_t dst = sbase + stage * SM_STAGE + (uint32_t)t * SM_TILE
                     + (uint32_t)(r * 128) + (uint32_t)((i16 ^ (r & 7)) << 4);
        asm volatile("cp.async.cg.shared.global [%0], [%1], 16;" :: "r"(dst), "l"(gp));
    }
}

// ---------------- fused gram (single-product bf16 HMMA) + RBF mixture --------
__global__ __launch_bounds__(256, 2) void mmd_mma_kernel() {
    extern __shared__ char smem[];
    const uint32_t sbase = smem_u32_of(smem);
    int tid = threadIdx.x;
    int wid = tid >> 5, lane = tid & 31;

    int rem = blockIdx.x, ti = 0;
    while (rem >= GRID_T - ti) { rem -= GRID_T - ti; ti++; }
    int tj = ti + rem;
    int rowA0 = ti * TILE, rowB0 = tj * TILE;

    float* sqA_s = (float*)(smem + SM_SQA);
    float* sqB_s = (float*)(smem + SM_SQB);
    if (tid < 128) sqA_s[tid] = g_sq[rowA0 + tid];
    else           sqB_s[tid - 128] = g_sq[rowB0 + (tid - 128)];

    // prologue: chunks 0,1 -> stages 0,1
    load_chunk_async(sbase, 0, 0, rowA0, rowB0, tid);
    asm volatile("cp.async.commit_group;" ::: "memory");
    load_chunk_async(sbase, 1, 1, rowA0, rowB0, tid);
    asm volatile("cp.async.commit_group;" ::: "memory");

    // warp tiling: 2 (rows) x 4 (cols) warps; warp tile 64x32
    int wr = wid >> 2, wc = wid & 3;
    int rA = wr * 64 + (lane & 15);
    int kgA = lane >> 4;
    int xrA = rA & 7;
    uint32_t aAddr[4];
#pragma unroll
    for (int mi = 0; mi < 4; mi++)
        aAddr[mi] = sbase + (uint32_t)((rA + mi * 16) * 128);
    int nB = wc * 32 + (lane & 7) + ((lane >> 4) << 3);
    int kgB = (lane >> 3) & 1;
    int xrB = nB & 7;
    uint32_t bAddr[2];
#pragma unroll
    for (int nb = 0; nb < 2; nb++)
        bAddr[nb] = sbase + SM_TILE + (uint32_t)((nB + nb * 16) * 128);

    float acc[4][4][4];
#pragma unroll
    for (int i = 0; i < 4; i++)
#pragma unroll
        for (int j = 0; j < 4; j++)
#pragma unroll
            for (int e = 0; e < 4; e++) acc[i][j][e] = 0.f;

    int stage = 0;
    for (int c = 0; c < NCHUNK; c++) {
        if (c + 1 < NCHUNK) asm volatile("cp.async.wait_group 1;" ::: "memory");
        else                asm volatile("cp.async.wait_group 0;" ::: "memory");
        __syncthreads();
        // barrier proves compute of chunk c-1 done => its stage (= (c+2)%3) is free
        if (c + 2 < NCHUNK) {
            int sn = stage + 2; if (sn >= 3) sn -= 3;
            load_chunk_async(sbase, (uint32_t)sn, c + 2, rowA0, rowB0, tid);
            asm volatile("cp.async.commit_group;" ::: "memory");
        }
        uint32_t stoff = (uint32_t)stage * SM_STAGE;
#pragma unroll
        for (int s = 0; s < 4; s++) {
            uint32_t colA = (uint32_t)(((s * 2 + kgA) ^ xrA) << 4);
            uint32_t colB = (uint32_t)(((s * 2 + kgB) ^ xrB) << 4);
            uint32_t ah[4][4], bh[2][4];
#pragma unroll
            for (int mi = 0; mi < 4; mi++)
                LDSM_X4(ah[mi], aAddr[mi] + stoff + colA);
#pragma unroll
            for (int nb = 0; nb < 2; nb++)
                LDSM_X4(bh[nb], bAddr[nb] + stoff + colB);
#pragma unroll
            for (int mi = 0; mi < 4; mi++) {
#pragma unroll
                for (int ni = 0; ni < 4; ni++) {
                    int nb = ni >> 1, j = ni & 1;
                    MMA_BF16(acc[mi][ni], ah[mi], bh[nb][2 * j], bh[nb][2 * j + 1]);
                }
            }
        }
        stage++; if (stage >= 3) stage = 0;
    }

    // epilogue: RBF mixture from register accumulators
    float coef = g_coef;
    float part = 0.f;
    int re = wr * 64 + (lane >> 2);
    int ce = wc * 32 + (lane & 3) * 2;
#pragma unroll
    for (int mi = 0; mi < 4; mi++) {
#pragma unroll
        for (int ni = 0; ni < 4; ni++) {
            int row = re + mi * 16;
            int col = ce + ni * 8;
#pragma unroll
            for (int e = 0; e < 4; e++) {
                float sA = sqA_s[row + ((e >> 1) << 3)];
                float sB = sqB_s[col + (e & 1)];
                float L2 = sA + sB - 2.f * acc[mi][ni][e];
                float t;
                asm("ex2.approx.ftz.f32 %0, %1;" : "=f"(t) : "f"(L2 * coef));
                float t2 = t * t, t4 = t2 * t2, t8 = t4 * t4, t16 = t8 * t8;
                part += t + t2 + t4 + t8 + t16;
            }
        }
    }

    float* red = (float*)(smem + SM_RED);
    red[tid] = part;
    __syncthreads();
#pragma unroll
    for (int o = 128; o; o >>= 1) {
        if (tid < o) red[tid] += red[tid + o];
        __syncthreads();
    }
    if (tid == 0) {
        float sign = ((ti < GRID_T / 2) == (tj < GRID_T / 2)) ? 1.f : -1.f;
        float wgt = (ti == tj) ? 1.f : 2.f;
        g_partials[blockIdx.x] = red[0] * sign * wgt;
    }
}

__global__ void reduce_kernel(float* __restrict__ out) {
    __shared__ double sh[64];
    int t = threadIdx.x;
    double a = 0.0;
    for (int i = t; i < NUM_TILES; i += 64) a += (double)g_partials[i];
    sh[t] = a; __syncthreads();
    for (int o = 32; o; o >>= 1) { if (t < o) sh[t] += sh[t + o]; __syncthreads(); }
    if (t == 0) out[0] = (float)(sh[0] / ((double)N_HALF * (double)N_HALF));
}

extern "C" void kernel_launch(void* const* d_in, const int* in_sizes, int n_in,
                              void* d_out, int out_size) {
    const float* src = (const float*)d_in[0];
    const float* tgt = (const float*)d_in[1];
    cudaFuncSetAttribute(mmd_mma_kernel, cudaFuncAttributeMaxDynamicSharedMemorySize,
                         SMEM_TOTAL);
    convert_kernel<<<CONV_CTAS, 256>>>(src, tgt);
    colsum_bw_kernel<<<CS_CTAS, 256>>>();
    mmd_mma_kernel<<<NUM_TILES, 256, SMEM_TOTAL>>>();
    reduce_kernel<<<1, 64>>>((float*)d_out);
}

// round 17
// speedup vs baseline: 1.0483x; 1.0483x over previous
#include <cuda_runtime.h>
#include <cuda_bf16.h>
#include <stdint.h>

#define N_HALF 4096
#define N_TOT  8192
#define DIM    512
#define TILE   128
#define NCHUNK 8
#define GRID_T 64
#define NUM_TILES 2080
#define PREP_CTAS (N_TOT / 8)
#define STRIPES 16
#define PITCH 516

__device__ __nv_bfloat16 g_hi[(size_t)N_TOT * DIM];
__device__ float g_sq[N_TOT];
__device__ float g_colpart[STRIPES][DIM];   // statically zero-init; self-cleaned
__device__ float g_coef;
__device__ __align__(16) float g_partials[NUM_TILES];
__device__ int g_prep_done;                 // self-cleaned

__device__ __forceinline__ uint32_t smem_u32_of(const void* p) {
    uint32_t a;
    asm("{ .reg .u64 t; cvta.to.shared.u64 t, %1; cvt.u32.u64 %0, t; }" : "=r"(a) : "l"(p));
    return a;
}

#define LDSM_X4(r, addr)                                                       \
    asm volatile("ldmatrix.sync.aligned.m8n8.x4.shared.b16 {%0,%1,%2,%3}, [%4];" \
        : "=r"((r)[0]), "=r"((r)[1]), "=r"((r)[2]), "=r"((r)[3]) : "r"(addr))

#define MMA_BF16(c, a, b0, b1)                                                 \
    asm volatile("mma.sync.aligned.m16n8k16.row.col.f32.bf16.bf16.f32 "        \
        "{%0,%1,%2,%3},{%4,%5,%6,%7},{%8,%9},{%0,%1,%2,%3};"                   \
        : "+f"((c)[0]), "+f"((c)[1]), "+f"((c)[2]), "+f"((c)[3])               \
        : "r"((a)[0]), "r"((a)[1]), "r"((a)[2]), "r"((a)[3]), "r"(b0), "r"(b1))

// ---------------- mmd smem map (bytes) ----------------
#define SM_TILE    16384
#define SM_STAGE   32768
#define SM_SQA     98304
#define SM_SQB     (SM_SQA + 512)
#define SM_RED     (SM_SQB + 512)
#define SMEM_TOTAL (SM_RED + 1024)

// ------- prep: cp.async-staged rows, column-owned colsum, 16-stripe atomics --
__global__ __launch_bounds__(256) void prep_kernel(const float* __restrict__ src,
                                                   const float* __restrict__ tgt) {
    __shared__ float stage[8 * PITCH];
    __shared__ int is_last;
    __shared__ double shd[256];
    int tid = threadIdx.x, w = tid >> 5, lane = tid & 31;
    int row0 = blockIdx.x * 8;
    const float* base = (row0 < N_HALF) ? src + (size_t)row0 * DIM
                                        : tgt + (size_t)(row0 - N_HALF) * DIM;
    uint32_t sstage = smem_u32_of(stage);

    // bulk-stage 8 rows (32KB) via cp.async: 1024 x 16B chunks
#pragma unroll
    for (int m = 0; m < 4; m++) {
        int u = tid + 256 * m;
        int r = u >> 7, j = u & 127;
        const char* gp = (const char*)(base + (size_t)r * DIM) + j * 16;
        uint32_t dst = sstage + (uint32_t)(r * PITCH * 4 + j * 16);
        asm volatile("cp.async.cg.shared.global [%0], [%1], 16;" :: "r"(dst), "l"(gp));
    }
    asm volatile("cp.async.commit_group;" ::: "memory");
    asm volatile("cp.async.wait_group 0;" ::: "memory");
    __syncthreads();

    // convert row w (cols lane*16 .. +15), rounded sq, store bf16
    const float4* rp = (const float4*)(stage + w * PITCH + lane * 16);
    float4 v0 = rp[0], v1 = rp[1], v2 = rp[2], v3 = rp[3];
    float f[16];
    f[0]=v0.x; f[1]=v0.y; f[2]=v0.z; f[3]=v0.w;
    f[4]=v1.x; f[5]=v1.y; f[6]=v1.z; f[7]=v1.w;
    f[8]=v2.x; f[9]=v2.y; f[10]=v2.z; f[11]=v2.w;
    f[12]=v3.x; f[13]=v3.y; f[14]=v3.z; f[15]=v3.w;
    uint32_t packed[8];
    float sq = 0.f;
#pragma unroll
    for (int k = 0; k < 8; k++) {
        __nv_bfloat16 ha = __float2bfloat16(f[2 * k]);
        __nv_bfloat16 hb = __float2bfloat16(f[2 * k + 1]);
        float fa = __bfloat162float(ha);
        float fb = __bfloat162float(hb);
        sq += fa * fa + fb * fb;
        __nv_bfloat162 h2; h2.x = ha; h2.y = hb;
        packed[k] = *(uint32_t*)&h2;
    }
    uint4* dst = (uint4*)(g_hi + (size_t)(row0 + w) * DIM + lane * 16);
    dst[0] = make_uint4(packed[0], packed[1], packed[2], packed[3]);
    dst[1] = make_uint4(packed[4], packed[5], packed[6], packed[7]);
#pragma unroll
    for (int o = 16; o; o >>= 1) sq += __shfl_xor_sync(0xffffffffu, sq, o);
    if (lane == 0) g_sq[row0 + w] = sq;

    // column-owned raw colsum over the 8 staged rows (cols 2t, 2t+1)
    float csx = 0.f, csy = 0.f;
#pragma unroll
    for (int r = 0; r < 8; r++) {
        csx += stage[r * PITCH + 2 * tid];
        csy += stage[r * PITCH + 2 * tid + 1];
    }
    int stripe = blockIdx.x & (STRIPES - 1);
    atomicAdd(&g_colpart[stripe][2 * tid], csx);
    atomicAdd(&g_colpart[stripe][2 * tid + 1], csy);

    // ---- last-CTA-done: compute bandwidth coefficient ----
    if (tid == 0) {
        __threadfence();
        int d = atomicAdd(&g_prep_done, 1);
        is_last = (d == PREP_CTAS - 1);
    }
    __syncthreads();
    if (!is_last) return;
    __threadfence();

    double acc = 0.0;
    for (int i = tid; i < N_TOT; i += 256) acc += (double)g_sq[i];
    shd[tid] = acc; __syncthreads();
    for (int o = 128; o; o >>= 1) { if (tid < o) shd[tid] += shd[tid + o]; __syncthreads(); }
    double sumsq = shd[0];
    __syncthreads();
    double acc2 = 0.0;
    for (int i = tid; i < DIM; i += 256) {
        double c = 0.0;
#pragma unroll
        for (int st = 0; st < STRIPES; st++) c += (double)g_colpart[st][i];
        acc2 += c * c;
    }
    shd[tid] = acc2; __syncthreads();
    for (int o = 128; o; o >>= 1) { if (tid < o) shd[tid] += shd[tid + o]; __syncthreads(); }
    if (tid == 0) {
        double ss = shd[0];
        double sumL2 = 2.0 * (double)N_TOT * sumsq - 2.0 * ss;
        double bw = sumL2 / ((double)N_TOT * (double)N_TOT - (double)N_TOT);
        g_coef = (float)(-1.4426950408889634 / (4.0 * bw));
        g_prep_done = 0;                   // self-clean
    }
    for (int i = tid; i < STRIPES * DIM; i += 256)
        ((float*)g_colpart)[i] = 0.f;      // self-clean
}

// ---------------- async tile loader (2 tiles: Ahi, Bhi) ----------------
__device__ __forceinline__ void load_chunk_async(uint32_t sbase, uint32_t stage, int c,
                                                 int rowA0, int rowB0, int tid) {
#pragma unroll
    for (int m = 0; m < 8; m++) {
        int u = tid + 256 * m;
        int t = u >> 10;            // 0: Ahi, 1: Bhi
        int v = u & 1023;
        int r = v >> 3;             // row 0..127
        int i16 = v & 7;            // 16B group within 128B row
        int grow = ((t == 0) ? rowA0 : rowB0) + r;
        const char* gp = (const char*)(g_hi + (size_t)grow * DIM) + c * 128 + i16 * 16;
        uint32_t dst = sbase + stage * SM_STAGE + (uint32_t)t * SM_TILE
                     + (uint32_t)(r * 128) + (uint32_t)((i16 ^ (r & 7)) << 4);
        asm volatile("cp.async.cg.shared.global [%0], [%1], 16;" :: "r"(dst), "l"(gp));
    }
}

// ---------------- fused gram (single-product bf16 HMMA) + RBF mixture --------
__global__ __launch_bounds__(256, 2) void mmd_mma_kernel() {
    extern __shared__ char smem[];
    const uint32_t sbase = smem_u32_of(smem);
    int tid = threadIdx.x;
    int wid = tid >> 5, lane = tid & 31;

    int rem = blockIdx.x, ti = 0;
    while (rem >= GRID_T - ti) { rem -= GRID_T - ti; ti++; }
    int tj = ti + rem;
    int rowA0 = ti * TILE, rowB0 = tj * TILE;

    float* sqA_s = (float*)(smem + SM_SQA);
    float* sqB_s = (float*)(smem + SM_SQB);
    if (tid < 128) sqA_s[tid] = g_sq[rowA0 + tid];
    else           sqB_s[tid - 128] = g_sq[rowB0 + (tid - 128)];

    // prologue: chunks 0,1 -> stages 0,1
    load_chunk_async(sbase, 0, 0, rowA0, rowB0, tid);
    asm volatile("cp.async.commit_group;" ::: "memory");
    load_chunk_async(sbase, 1, 1, rowA0, rowB0, tid);
    asm volatile("cp.async.commit_group;" ::: "memory");

    // warp tiling: 2 (rows) x 4 (cols) warps; warp tile 64x32
    int wr = wid >> 2, wc = wid & 3;
    int rA = wr * 64 + (lane & 15);
    int kgA = lane >> 4;
    int xrA = rA & 7;
    uint32_t aAddr[4];
#pragma unroll
    for (int mi = 0; mi < 4; mi++)
        aAddr[mi] = sbase + (uint32_t)((rA + mi * 16) * 128);
    int nB = wc * 32 + (lane & 7) + ((lane >> 4) << 3);
    int kgB = (lane >> 3) & 1;
    int xrB = nB & 7;
    uint32_t bAddr[2];
#pragma unroll
    for (int nb = 0; nb < 2; nb++)
        bAddr[nb] = sbase + SM_TILE + (uint32_t)((nB + nb * 16) * 128);

    float acc[4][4][4];
#pragma unroll
    for (int i = 0; i < 4; i++)
#pragma unroll
        for (int j = 0; j < 4; j++)
#pragma unroll
            for (int e = 0; e < 4; e++) acc[i][j][e] = 0.f;

    int stage = 0;
    for (int c = 0; c < NCHUNK; c++) {
        if (c + 1 < NCHUNK) asm volatile("cp.async.wait_group 1;" ::: "memory");
        else                asm volatile("cp.async.wait_group 0;" ::: "memory");
        __syncthreads();
        // barrier proves compute of chunk c-1 done => its stage (= (c+2)%3) is free
        if (c + 2 < NCHUNK) {
            int sn = stage + 2; if (sn >= 3) sn -= 3;
            load_chunk_async(sbase, (uint32_t)sn, c + 2, rowA0, rowB0, tid);
            asm volatile("cp.async.commit_group;" ::: "memory");
        }
        uint32_t stoff = (uint32_t)stage * SM_STAGE;
#pragma unroll
        for (int s = 0; s < 4; s++) {
            uint32_t colA = (uint32_t)(((s * 2 + kgA) ^ xrA) << 4);
            uint32_t colB = (uint32_t)(((s * 2 + kgB) ^ xrB) << 4);
            uint32_t ah[4][4], bh[2][4];
#pragma unroll
            for (int mi = 0; mi < 4; mi++)
                LDSM_X4(ah[mi], aAddr[mi] + stoff + colA);
#pragma unroll
            for (int nb = 0; nb < 2; nb++)
                LDSM_X4(bh[nb], bAddr[nb] + stoff + colB);
#pragma unroll
            for (int mi = 0; mi < 4; mi++) {
#pragma unroll
                for (int ni = 0; ni < 4; ni++) {
                    int nb = ni >> 1, j = ni & 1;
                    MMA_BF16(acc[mi][ni], ah[mi], bh[nb][2 * j], bh[nb][2 * j + 1]);
                }
            }
        }
        stage++; if (stage >= 3) stage = 0;
    }

    // epilogue: RBF mixture from register accumulators
    float coef = g_coef;
    float part = 0.f;
    int re = wr * 64 + (lane >> 2);
    int ce = wc * 32 + (lane & 3) * 2;
#pragma unroll
    for (int mi = 0; mi < 4; mi++) {
#pragma unroll
        for (int ni = 0; ni < 4; ni++) {
            int row = re + mi * 16;
            int col = ce + ni * 8;
#pragma unroll
            for (int e = 0; e < 4; e++) {
                float sA = sqA_s[row + ((e >> 1) << 3)];
                float sB = sqB_s[col + (e & 1)];
                float L2 = sA + sB - 2.f * acc[mi][ni][e];
                float t;
                asm("ex2.approx.ftz.f32 %0, %1;" : "=f"(t) : "f"(L2 * coef));
                float t2 = t * t, t4 = t2 * t2, t8 = t4 * t4, t16 = t8 * t8;
                part += t + t2 + t4 + t8 + t16;
            }
        }
    }

    float* red = (float*)(smem + SM_RED);
    red[tid] = part;
    __syncthreads();
#pragma unroll
    for (int o = 128; o; o >>= 1) {
        if (tid < o) red[tid] += red[tid + o];
        __syncthreads();
    }
    if (tid == 0) {
        float sign = ((ti < GRID_T / 2) == (tj < GRID_T / 2)) ? 1.f : -1.f;
        float wgt = (ti == tj) ? 1.f : 2.f;
        g_partials[blockIdx.x] = red[0] * sign * wgt;
    }
}

// ---- parallel final reduce: 256 threads, float4 loads (MLP >= 2) ----
__global__ __launch_bounds__(256) void reduce_kernel(float* __restrict__ out) {
    __shared__ double sh[256];
    int t = threadIdx.x;
    const float4* p4 = (const float4*)g_partials;   // 2080/4 = 520 vectors
    double a = 0.0;
    // front-batch: i, i+256, i+512 are independent
    float4 v0 = p4[t];
    float4 v1 = p4[t + 256];
    a += (double)v0.x + v0.y + v0.z + v0.w;
    a += (double)v1.x + v1.y + v1.z + v1.w;
    if (t < 8) {
        float4 v2 = p4[t + 512];
        a += (double)v2.x + v2.y + v2.z + v2.w;
    }
    sh[t] = a; __syncthreads();
#pragma unroll
    for (int o = 128; o; o >>= 1) { if (t < o) sh[t] += sh[t + o]; __syncthreads(); }
    if (t == 0) out[0] = (float)(sh[0] / ((double)N_HALF * (double)N_HALF));
}

extern "C" void kernel_launch(void* const* d_in, const int* in_sizes, int n_in,
                              void* d_out, int out_size) {
    const float* src = (const float*)d_in[0];
    const float* tgt = (const float*)d_in[1];
    cudaFuncSetAttribute(mmd_mma_kernel, cudaFuncAttributeMaxDynamicSharedMemorySize,
                         SMEM_TOTAL);
    prep_kernel<<<PREP_CTAS, 256>>>(src, tgt);
    mmd_mma_kernel<<<NUM_TILES, 256, SMEM_TOTAL>>>();
    reduce_kernel<<<1, 256>>>((float*)d_out);
}